// round 2
// baseline (speedup 1.0000x reference)
#include <cuda_runtime.h>

// Problem constants (fixed shapes from reference)
#define BB 64
#define LL 512
#define HH 768
#define WW 255
#define H4 (HH / 4)   // 192 float4 per row

// Scratch: word start offsets (1 + exclusive prefix sum of lengths)
__device__ int g_starts[BB * WW];

// Kernel 1: per-batch inclusive scan of words_lengths -> starts
__global__ void wordrep_scan_kernel(const int* __restrict__ wl) {
    __shared__ int s[256];
    const int b = blockIdx.x;
    const int t = threadIdx.x;  // 256 threads
    int v = (t < WW) ? wl[b * WW + t] : 0;
    s[t] = v;
    __syncthreads();
    #pragma unroll
    for (int off = 1; off < 256; off <<= 1) {
        int add = (t >= off) ? s[t - off] : 0;
        __syncthreads();
        s[t] += add;
        __syncthreads();
    }
    if (t < WW) {
        int excl = (t == 0) ? 0 : s[t - 1];
        g_starts[b * WW + t] = 1 + excl;  // tokens start at index 1 (token 0 is CLS)
    }
}

// Kernel 2: one block per (b, word) + extra column for CLS copy.
// 192 threads, each moves one float4 of the H=768 row.
__global__ void wordrep_gather_kernel(const float4* __restrict__ seq,
                                      const int* __restrict__ wl,
                                      float4* __restrict__ out) {
    const int w = blockIdx.x;   // 0..WW-1 words, WW == cls copy
    const int b = blockIdx.y;
    const int t = threadIdx.x;  // 0..191

    if (w == WW) {
        // cls_output[b,:] = seq[b,0,:]
        out[(size_t)b * H4 + t] = seq[((size_t)b * LL) * H4 + t];
        return;
    }

    const int len   = wl[b * WW + w];
    const int start = g_starts[b * WW + w];

    float4 acc = make_float4(0.f, 0.f, 0.f, 0.f);
    for (int l = 0; l < len; ++l) {
        const int tok = start + l;
        if (tok < LL) {  // reference truncates tokens beyond L
            float4 x = seq[((size_t)b * LL + tok) * H4 + t];
            acc.x += x.x; acc.y += x.y; acc.z += x.z; acc.w += x.w;
        }
    }

    float4 r;
    if (len > 0) {
        const float inv = 1.0f / (float)len;
        r = make_float4(acc.x * inv, acc.y * inv, acc.z * inv, acc.w * inv);
    } else {
        r = make_float4(0.f, 0.f, 0.f, 0.f);  // words_lengths<=0 -> zeros (per reference)
    }

    // Output layout: [cls (B*H floats)] then [context (B*W*H floats)]
    out[(size_t)BB * H4 + ((size_t)b * WW + w) * H4 + t] = r;
}

extern "C" void kernel_launch(void* const* d_in, const int* in_sizes, int n_in,
                              void* d_out, int out_size) {
    (void)in_sizes; (void)n_in; (void)out_size;
    const float4* seq = (const float4*)d_in[0];     // sequence_output (B,L,H) f32
    const int*    wl  = (const int*)d_in[1];        // words_lengths (B,W) i32
    float4*       out = (float4*)d_out;

    wordrep_scan_kernel<<<BB, 256>>>(wl);
    dim3 grid(WW + 1, BB);
    wordrep_gather_kernel<<<grid, H4>>>(seq, wl, out);
}

// round 3
// speedup vs baseline: 1.1935x; 1.1935x over previous
#include <cuda_runtime.h>

// Fixed shapes from reference
#define BB 64
#define LL 512
#define HH 768
#define WW 255
#define H4 (HH / 4)      // 192 float4 per H row
#define WPB 4            // words per block
#define NCHUNK 64        // ceil(255/4); blockIdx.x == NCHUNK -> cls copy
#define NWARPS 6         // 192 / 32

// One fused kernel: per-block prefix-sum of words_lengths (cheap, L2-hot)
// + mean-pool 4 consecutive words (contiguous token rows -> streaming reads).
__global__ __launch_bounds__(192) void wordrep_fused_kernel(
        const float4* __restrict__ seq,   // (B, L, H) as float4[B*L*H4]
        const int*    __restrict__ wl,    // (B, W)
        float4*       __restrict__ out)   // [cls B*H4][ctx B*W*H4]
{
    const int b = blockIdx.y;
    const int c = blockIdx.x;
    const int t = threadIdx.x;            // 0..191

    if (c == NCHUNK) {
        // cls_output[b,:] = seq[b,0,:]
        out[(size_t)b * H4 + t] = seq[(size_t)b * LL * H4 + t];
        return;
    }

    const int w0 = c * WPB;

    // ---- fused per-block scan: base = 1 + sum(wl[b, 0..w0-1]) ----
    __shared__ int s_part[NWARPS];
    __shared__ int s_len[WPB];

    const int* wlb = wl + b * WW;
    int psum = 0;
    // each thread covers indices t, t+192 (w0 <= 252 so <= 2 loads)
    #pragma unroll
    for (int i = t; i < w0; i += 192) psum += wlb[i];
    #pragma unroll
    for (int o = 16; o > 0; o >>= 1)
        psum += __shfl_down_sync(0xffffffffu, psum, o);
    if ((t & 31) == 0) s_part[t >> 5] = psum;
    if (t < WPB) s_len[t] = (w0 + t < WW) ? wlb[w0 + t] : 0;
    __syncthreads();

    int base = 1;
    #pragma unroll
    for (int i = 0; i < NWARPS; i++) base += s_part[i];

    // ---- per-word starts (compile-time register indices only) ----
    int len[WPB], st[WPB];
    {
        int run = base;
        #pragma unroll
        for (int w = 0; w < WPB; w++) { len[w] = s_len[w]; st[w] = run; run += len[w]; }
    }

    const size_t rowb = (size_t)b * LL;

    // ---- issue all loads up front: 4 + 4 independent LDG.128 per thread ----
    float4 a[WPB], a2[WPB];
    #pragma unroll
    for (int w = 0; w < WPB; w++)
        if (len[w] > 0 && st[w] < LL)
            a[w] = seq[(rowb + st[w]) * H4 + t];
    #pragma unroll
    for (int w = 0; w < WPB; w++)
        if (len[w] > 1 && st[w] + 1 < LL)
            a2[w] = seq[(rowb + st[w] + 1) * H4 + t];

    // ---- combine + store (coalesced, consecutive output rows) ----
    const size_t ctx = (size_t)BB * H4;
    #pragma unroll
    for (int w = 0; w < WPB; w++) {
        const int gw = w0 + w;
        if (gw >= WW) continue;
        float4 r;
        if (len[w] > 0) {
            r = a[w];
            if (len[w] > 1 && st[w] + 1 < LL) {
                r.x += a2[w].x; r.y += a2[w].y; r.z += a2[w].z; r.w += a2[w].w;
            }
            // len in {1,2}: exact reciprocals via select; generic fallback otherwise
            float inv = (len[w] == 1) ? 1.0f : (len[w] == 2) ? 0.5f
                                             : 1.0f / (float)len[w];
            r.x *= inv; r.y *= inv; r.z *= inv; r.w *= inv;
        } else {
            r = make_float4(0.f, 0.f, 0.f, 0.f);   // words_lengths<=0 -> zeros
        }
        out[ctx + ((size_t)b * WW + gw) * H4 + t] = r;
    }
}

extern "C" void kernel_launch(void* const* d_in, const int* in_sizes, int n_in,
                              void* d_out, int out_size) {
    (void)in_sizes; (void)n_in; (void)out_size;
    const float4* seq = (const float4*)d_in[0];
    const int*    wl  = (const int*)d_in[1];
    float4*       out = (float4*)d_out;

    dim3 grid(NCHUNK + 1, BB);   // 65 x 64 = 4160 blocks
    wordrep_fused_kernel<<<grid, H4>>>(seq, wl, out);
}